// round 11
// baseline (speedup 1.0000x reference)
#include <cuda_runtime.h>

#define B_TOTAL 262144
#define TPB 256
#define ROWS_CTA 256
#define NBLK (B_TOTAL / ROWS_CTA)      // 1024

#define WT_STRIDE 68
#define WT_LAYER (64 * WT_STRIDE)      // 4352
#define WT_TOTAL (3 * WT_LAYER)        // 13056
#define BC_OFF WT_TOTAL                // bc[3][128]: bias[64] | c0[64]
#define X_STRIDE 68
#define XA_OFF (BC_OFF + 384)
#define X_FLOATS (ROWS_CTA * X_STRIDE) // 17408
#define XB_OFF (XA_OFF + X_FLOATS)
#define SMEM_FLOATS (XB_OFF + X_FLOATS)  // 48256
#define SMEM_BYTES (SMEM_FLOATS * 4)     // 193024 B -> 1 CTA/SM, 8 warps

typedef unsigned long long ull;

__device__ __forceinline__ void ffma2(ull& d, ull a, ull b) {
    asm("fma.rn.f32x2 %0, %1, %2, %0;" : "+l"(d) : "l"(a), "l"(b));
}
__device__ __forceinline__ float pairsum(ull v) {
    float lo, hi;
    asm("mov.b64 {%0, %1}, %2;" : "=f"(lo), "=f"(hi) : "l"(v));
    return lo + hi;
}
__device__ __forceinline__ ull pack2(float lo, float hi) {
    ull r;
    asm("mov.b64 %0, {%1, %2};" : "=l"(r) : "f"(lo), "f"(hi));
    return r;
}
__device__ __forceinline__ float2 unpk(ull v) {
    float lo, hi;
    asm("mov.b64 {%0, %1}, %2;" : "=f"(lo), "=f"(hi) : "l"(v));
    return make_float2(lo, hi);
}
// Zero pair lanes per mask bits (2q, 2q+1) of m.
__device__ __forceinline__ ull maskpair(ull v, ull m, int q) {
    ull mm = (((m >> (2 * q)) & 1ull) * 0x00000000FFFFFFFFull)
           | (((m >> (2 * q + 1)) & 1ull) * 0xFFFFFFFF00000000ull);
    return v & mm;
}

// ---------------------------------------------------------------------------
// Forward GEMM tile: C[r][j] = t*c0[j] (+ sum_k X[r][k]*Wt[k][j]) + bias[j].
// k-streaming single-accumulator per C element = cuBLAS-exact rounding order
// (bit-identical to R3..R10 passing chains). Thread rows: R0 + 8*i (i=0..7),
// cols: J0 + jj (jj=0..7). RELU=1 -> clamp + record mask bits (i*8+jj).
// ---------------------------------------------------------------------------
template <int RELU>
__device__ __forceinline__ void gemm_fwd(
    const float* __restrict__ Wt, const float* __restrict__ bc,
    const float* __restrict__ Xin, float* __restrict__ Xout,
    float t, int R0, int J0, ull& mask) {
    float C[8][8];
#pragma unroll
    for (int jj = 0; jj < 8; jj++) {
        float cj = t * bc[64 + J0 + jj];
#pragma unroll
        for (int i = 0; i < 8; i++) C[i][jj] = cj;
    }
#pragma unroll 1
    for (int k4 = 0; k4 < 16; k4++) {
        float4 a4[8];
#pragma unroll
        for (int i = 0; i < 8; i++)
            a4[i] = *(const float4*)(Xin + (R0 + 8 * i) * X_STRIDE + 4 * k4);
#pragma unroll
        for (int kk = 0; kk < 4; kk++) {
            int k = 4 * k4 + kk;
            const float4* bp = (const float4*)(Wt + k * WT_STRIDE + J0);
            float4 b0 = bp[0], b1 = bp[1];
            float B[8] = {b0.x, b0.y, b0.z, b0.w, b1.x, b1.y, b1.z, b1.w};
#pragma unroll
            for (int i = 0; i < 8; i++) {
                float a = (kk == 0) ? a4[i].x : (kk == 1) ? a4[i].y
                        : (kk == 2) ? a4[i].z : a4[i].w;
#pragma unroll
                for (int jj = 0; jj < 8; jj++)
                    C[i][jj] = fmaf(a, B[jj], C[i][jj]);
            }
        }
    }
#pragma unroll
    for (int i = 0; i < 8; i++) {
        float s[8];
#pragma unroll
        for (int jj = 0; jj < 8; jj++) {
            float v = C[i][jj] + bc[J0 + jj];
            if (RELU) {
                if (v > 0.0f) mask |= 1ull << (i * 8 + jj); else v = 0.0f;
            }
            s[jj] = v;
        }
        float* o = Xout + (R0 + 8 * i) * X_STRIDE + J0;
        *(float4*)(o) = make_float4(s[0], s[1], s[2], s[3]);
        *(float4*)(o + 4) = make_float4(s[4], s[5], s[6], s[7]);
    }
}

// ---------------------------------------------------------------------------
// Backward GEMM tile (continuous path): same contraction, FFMA2 on OUTPUT
// pairs: C[i][jp] (pair j=2jp,2jp+1) += (a,a)*(w_j, w_j+1). Same Wt, same
// thread tiling as forward -> mask bits are thread-local.
// ---------------------------------------------------------------------------
template <int MASKED>
__device__ __forceinline__ void gemm_bwd(
    const float* __restrict__ Wt,
    const float* __restrict__ Xin, float* __restrict__ Xout,
    int R0, int J0, ull mask) {
    ull C[8][4];
#pragma unroll
    for (int i = 0; i < 8; i++)
#pragma unroll
        for (int jp = 0; jp < 4; jp++) C[i][jp] = 0ull;
#pragma unroll 1
    for (int k4 = 0; k4 < 16; k4++) {
        float4 a4[8];
#pragma unroll
        for (int i = 0; i < 8; i++)
            a4[i] = *(const float4*)(Xin + (R0 + 8 * i) * X_STRIDE + 4 * k4);
#pragma unroll
        for (int kk = 0; kk < 4; kk++) {
            int k = 4 * k4 + kk;
            const ulonglong2* bp = (const ulonglong2*)(Wt + k * WT_STRIDE + J0);
            ulonglong2 w01 = bp[0], w23 = bp[1];
            ull bq[4] = {w01.x, w01.y, w23.x, w23.y};
#pragma unroll
            for (int i = 0; i < 8; i++) {
                float a = (kk == 0) ? a4[i].x : (kk == 1) ? a4[i].y
                        : (kk == 2) ? a4[i].z : a4[i].w;
                ull ap = pack2(a, a);
#pragma unroll
                for (int jp = 0; jp < 4; jp++)
                    ffma2(C[i][jp], ap, bq[jp]);
            }
        }
    }
#pragma unroll
    for (int i = 0; i < 8; i++) {
        float2 v[4];
#pragma unroll
        for (int jp = 0; jp < 4; jp++) {
            ull c = MASKED ? maskpair(C[i][jp], mask >> (i * 8), jp) : C[i][jp];
            v[jp] = unpk(c);
        }
        float* o = Xout + (R0 + 8 * i) * X_STRIDE + J0;
        *(float4*)(o) = make_float4(v[0].x, v[0].y, v[1].x, v[1].y);
        *(float4*)(o + 4) = make_float4(v[2].x, v[2].y, v[3].x, v[3].y);
    }
}

__global__ void __launch_bounds__(TPB)
ode_kernel(const float* __restrict__ tptr, const float* __restrict__ z,
           const float* __restrict__ e,
           const float* __restrict__ W0, const float* __restrict__ b0,
           const float* __restrict__ W1, const float* __restrict__ b1,
           const float* __restrict__ W2, const float* __restrict__ b2,
           float* __restrict__ zdot, float* __restrict__ negdiv) {
    extern __shared__ float sm[];
    const int tid = threadIdx.x;

    float* bc = sm + BC_OFF;
    float* Xa = sm + XA_OFF;
    float* Xb = sm + XB_OFF;

    // ---- Stage Wt[l][k][j] = W_l[j][k+1] (k-major), bias/c0 ----
    {
        const float* Wg[3] = {W0, W1, W2};
        const float* bg[3] = {b0, b1, b2};
        for (int idx = tid; idx < 3 * 4096; idx += TPB) {
            int k = idx & 63;
            int j = (idx >> 6) & 63;
            int l = idx >> 12;
            sm[l * WT_LAYER + k * WT_STRIDE + j] = Wg[l][j * 65 + 1 + k];
        }
        if (tid < 192) {
            int l = tid >> 6, j = tid & 63;
            bc[l * 128 + j] = bg[l][j];
            bc[l * 128 + 64 + j] = Wg[l][j * 65];   // t-column
        }
    }

    // ---- Stage z (row tid) into Xa ----
    {
        const float4* z4 = (const float4*)(z + ((size_t)blockIdx.x * ROWS_CTA + tid) * 64);
#pragma unroll
        for (int c = 0; c < 16; c++)
            *(float4*)(Xa + tid * X_STRIDE + 4 * c) = z4[c];
    }
    __syncthreads();

    const float t = tptr[0];
    const int lane = tid & 31, wid = tid >> 5;
    const int rg = lane & 7, jg = lane >> 3;
    const int R0 = (wid & 3) * 64 + rg;       // rows R0 + 8*i
    const int J0 = (wid >> 2) * 32 + 8 * jg;  // cols J0 + 0..7

    ull m0 = 0ull, m1 = 0ull, dummy = 0ull;

    // ---- Forward ----
    gemm_fwd<1>(sm,                bc,       Xa, Xb, t, R0, J0, m0);
    __syncthreads();
    gemm_fwd<1>(sm + WT_LAYER,     bc + 128, Xb, Xa, t, R0, J0, m1);
    __syncthreads();
    gemm_fwd<0>(sm + 2 * WT_LAYER, bc + 256, Xa, Xb, t, R0, J0, dummy);
    __syncthreads();

    // ---- z_dot flush (coalesced) ----
    {
        float4* dst = (float4*)(zdot + (size_t)blockIdx.x * ROWS_CTA * 64);
        for (int i4 = tid; i4 < ROWS_CTA * 16; i4 += TPB) {
            int r = i4 >> 4, c = (i4 & 15) << 2;
            dst[i4] = *(const float4*)(Xb + r * X_STRIDE + c);
        }
    }
    __syncthreads();

    // ---- Stage e (row tid) into Xa ----
    {
        const float4* e4 = (const float4*)(e + ((size_t)blockIdx.x * ROWS_CTA + tid) * 64);
#pragma unroll
        for (int c = 0; c < 16; c++)
            *(float4*)(Xa + tid * X_STRIDE + 4 * c) = e4[c];
    }
    __syncthreads();

    // ---- Backward chain: u = D0(W0c e); y = D1(W1c u); p = W2c y ----
    gemm_bwd<1>(sm,                Xa, Xb, R0, J0, m0);
    __syncthreads();
    gemm_bwd<1>(sm + WT_LAYER,     Xb, Xa, R0, J0, m1);
    __syncthreads();
    gemm_bwd<0>(sm + 2 * WT_LAYER, Xa, Xb, R0, J0, 0ull);
    __syncthreads();

    // ---- negdiv: div = e . p  (row tid; e re-read from gmem, L2-resident) ----
    {
        const int r = tid;
        const float4* e4 = (const float4*)(e + ((size_t)blockIdx.x * ROWS_CTA + r) * 64);
        ull dp = 0ull;
#pragma unroll
        for (int c = 0; c < 16; c++) {
            float4 ev = e4[c];
            float4 pv = *(const float4*)(Xb + r * X_STRIDE + 4 * c);
            ffma2(dp, pack2(ev.x, ev.y), pack2(pv.x, pv.y));
            ffma2(dp, pack2(ev.z, ev.w), pack2(pv.z, pv.w));
        }
        negdiv[(size_t)blockIdx.x * ROWS_CTA + r] = -pairsum(dp);
    }
}

extern "C" void kernel_launch(void* const* d_in, const int* in_sizes, int n_in,
                              void* d_out, int out_size) {
    const float* t  = (const float*)d_in[0];
    const float* z  = (const float*)d_in[1];
    const float* e  = (const float*)d_in[2];
    const float* W0 = (const float*)d_in[3];
    const float* b0 = (const float*)d_in[4];
    const float* W1 = (const float*)d_in[5];
    const float* b1 = (const float*)d_in[6];
    const float* W2 = (const float*)d_in[7];
    const float* b2 = (const float*)d_in[8];

    float* zdot = (float*)d_out;                       // [B, 64]
    float* negdiv = zdot + (size_t)B_TOTAL * 64;       // [B, 1]

    cudaFuncSetAttribute(ode_kernel, cudaFuncAttributeMaxDynamicSharedMemorySize, SMEM_BYTES);
    ode_kernel<<<NBLK, TPB, SMEM_BYTES>>>(t, z, e, W0, b0, W1, b1, W2, b2, zdot, negdiv);
}

// round 12
// speedup vs baseline: 1.0353x; 1.0353x over previous
#include <cuda_runtime.h>

#define B_TOTAL 262144
#define TPB 256
#define ROWS_CTA 256
#define NBLK (B_TOTAL / ROWS_CTA)      // 1024

#define WT_STRIDE 68
#define WT_LAYER (64 * WT_STRIDE)      // 4352
#define WT_TOTAL (3 * WT_LAYER)        // 13056
#define BC_OFF WT_TOTAL                // bc[3][128]: bias[64] | c0[64]
#define X_STRIDE 68
#define XA_OFF (BC_OFF + 384)
#define X_FLOATS (ROWS_CTA * X_STRIDE) // 17408
#define XB_OFF (XA_OFF + X_FLOATS)
#define SMEM_FLOATS (XB_OFF + X_FLOATS)  // 48256
#define SMEM_BYTES (SMEM_FLOATS * 4)     // 193024 B -> 1 CTA/SM, 8 warps

typedef unsigned long long ull;

__device__ __forceinline__ void ffma2(ull& d, ull a, ull b) {
    asm("fma.rn.f32x2 %0, %1, %2, %0;" : "+l"(d) : "l"(a), "l"(b));
}
__device__ __forceinline__ float pairsum(ull v) {
    float lo, hi;
    asm("mov.b64 {%0, %1}, %2;" : "=f"(lo), "=f"(hi) : "l"(v));
    return lo + hi;
}
__device__ __forceinline__ ull pack2(float lo, float hi) {
    ull r;
    asm("mov.b64 %0, {%1, %2};" : "=l"(r) : "f"(lo), "f"(hi));
    return r;
}
__device__ __forceinline__ float2 unpk(ull v) {
    float lo, hi;
    asm("mov.b64 {%0, %1}, %2;" : "=f"(lo), "=f"(hi) : "l"(v));
    return make_float2(lo, hi);
}
// Zero pair lanes per mask bits (2q, 2q+1) of m.
__device__ __forceinline__ ull maskpair(ull v, ull m, int q) {
    ull mm = (((m >> (2 * q)) & 1ull) * 0x00000000FFFFFFFFull)
           | (((m >> (2 * q + 1)) & 1ull) * 0xFFFFFFFF00000000ull);
    return v & mm;
}

// ---------------------------------------------------------------------------
// Forward GEMM tile, FFMA2 on OUTPUT pairs. Each packed lane is one output's
// single sequential k-ascending accumulator chain:
//   lane_j: init t*c0[j]; k ascending fmaf(a, w[k][j], .); final + bias[j]
// -> bit-identical rounding to the scalar cuBLAS chain (mask-exact), at half
// the fma-pipe issues. Thread tile rows R0+8i, col pairs J0+2jp.
// ---------------------------------------------------------------------------
template <int RELU>
__device__ __forceinline__ void gemm_fwd(
    const float* __restrict__ Wt, const float* __restrict__ bc,
    const float* __restrict__ Xin, float* __restrict__ Xout,
    float t, int R0, int J0, ull& mask) {
    ull C[8][4];
#pragma unroll
    for (int jp = 0; jp < 4; jp++) {
        ull cj = pack2(t * bc[64 + J0 + 2 * jp], t * bc[64 + J0 + 2 * jp + 1]);
#pragma unroll
        for (int i = 0; i < 8; i++) C[i][jp] = cj;
    }
#pragma unroll 1
    for (int k4 = 0; k4 < 16; k4++) {
        float4 a4[8];
#pragma unroll
        for (int i = 0; i < 8; i++)
            a4[i] = *(const float4*)(Xin + (R0 + 8 * i) * X_STRIDE + 4 * k4);
#pragma unroll
        for (int kk = 0; kk < 4; kk++) {
            int k = 4 * k4 + kk;
            const ulonglong2* bp = (const ulonglong2*)(Wt + k * WT_STRIDE + J0);
            ulonglong2 w01 = bp[0], w23 = bp[1];
            ull bq[4] = {w01.x, w01.y, w23.x, w23.y};
#pragma unroll
            for (int i = 0; i < 8; i++) {
                float a = (kk == 0) ? a4[i].x : (kk == 1) ? a4[i].y
                        : (kk == 2) ? a4[i].z : a4[i].w;
                ull ap = pack2(a, a);
#pragma unroll
                for (int jp = 0; jp < 4; jp++)
                    ffma2(C[i][jp], ap, bq[jp]);
            }
        }
    }
#pragma unroll
    for (int i = 0; i < 8; i++) {
        float s[8];
#pragma unroll
        for (int jp = 0; jp < 4; jp++) {
            float2 c = unpk(C[i][jp]);
            float v0 = c.x + bc[J0 + 2 * jp];
            float v1 = c.y + bc[J0 + 2 * jp + 1];
            if (RELU) {
                if (v0 > 0.0f) mask |= 1ull << (i * 8 + 2 * jp); else v0 = 0.0f;
                if (v1 > 0.0f) mask |= 1ull << (i * 8 + 2 * jp + 1); else v1 = 0.0f;
            }
            s[2 * jp] = v0; s[2 * jp + 1] = v1;
        }
        float* o = Xout + (R0 + 8 * i) * X_STRIDE + J0;
        *(float4*)(o) = make_float4(s[0], s[1], s[2], s[3]);
        *(float4*)(o + 4) = make_float4(s[4], s[5], s[6], s[7]);
    }
}

// ---------------------------------------------------------------------------
// Backward GEMM tile (continuous path): identical contraction, output-pair
// FFMA2, optional relu-mask application on the result.
// ---------------------------------------------------------------------------
template <int MASKED>
__device__ __forceinline__ void gemm_bwd(
    const float* __restrict__ Wt,
    const float* __restrict__ Xin, float* __restrict__ Xout,
    int R0, int J0, ull mask) {
    ull C[8][4];
#pragma unroll
    for (int i = 0; i < 8; i++)
#pragma unroll
        for (int jp = 0; jp < 4; jp++) C[i][jp] = 0ull;
#pragma unroll 1
    for (int k4 = 0; k4 < 16; k4++) {
        float4 a4[8];
#pragma unroll
        for (int i = 0; i < 8; i++)
            a4[i] = *(const float4*)(Xin + (R0 + 8 * i) * X_STRIDE + 4 * k4);
#pragma unroll
        for (int kk = 0; kk < 4; kk++) {
            int k = 4 * k4 + kk;
            const ulonglong2* bp = (const ulonglong2*)(Wt + k * WT_STRIDE + J0);
            ulonglong2 w01 = bp[0], w23 = bp[1];
            ull bq[4] = {w01.x, w01.y, w23.x, w23.y};
#pragma unroll
            for (int i = 0; i < 8; i++) {
                float a = (kk == 0) ? a4[i].x : (kk == 1) ? a4[i].y
                        : (kk == 2) ? a4[i].z : a4[i].w;
                ull ap = pack2(a, a);
#pragma unroll
                for (int jp = 0; jp < 4; jp++)
                    ffma2(C[i][jp], ap, bq[jp]);
            }
        }
    }
#pragma unroll
    for (int i = 0; i < 8; i++) {
        float2 v[4];
#pragma unroll
        for (int jp = 0; jp < 4; jp++) {
            ull c = MASKED ? maskpair(C[i][jp], mask >> (i * 8), jp) : C[i][jp];
            v[jp] = unpk(c);
        }
        float* o = Xout + (R0 + 8 * i) * X_STRIDE + J0;
        *(float4*)(o) = make_float4(v[0].x, v[0].y, v[1].x, v[1].y);
        *(float4*)(o + 4) = make_float4(v[2].x, v[2].y, v[3].x, v[3].y);
    }
}

__global__ void __launch_bounds__(TPB)
ode_kernel(const float* __restrict__ tptr, const float* __restrict__ z,
           const float* __restrict__ e,
           const float* __restrict__ W0, const float* __restrict__ b0,
           const float* __restrict__ W1, const float* __restrict__ b1,
           const float* __restrict__ W2, const float* __restrict__ b2,
           float* __restrict__ zdot, float* __restrict__ negdiv) {
    extern __shared__ float sm[];
    const int tid = threadIdx.x;

    float* bc = sm + BC_OFF;
    float* Xa = sm + XA_OFF;
    float* Xb = sm + XB_OFF;

    // ---- Stage Wt[l][k][j] = W_l[j][k+1] (k-major), bias/c0 ----
    {
        const float* Wg[3] = {W0, W1, W2};
        const float* bg[3] = {b0, b1, b2};
        for (int idx = tid; idx < 3 * 4096; idx += TPB) {
            int k = idx & 63;
            int j = (idx >> 6) & 63;
            int l = idx >> 12;
            sm[l * WT_LAYER + k * WT_STRIDE + j] = Wg[l][j * 65 + 1 + k];
        }
        if (tid < 192) {
            int l = tid >> 6, j = tid & 63;
            bc[l * 128 + j] = bg[l][j];
            bc[l * 128 + 64 + j] = Wg[l][j * 65];   // t-column
        }
    }

    // ---- Stage z (row tid) into Xa ----
    {
        const float4* z4 = (const float4*)(z + ((size_t)blockIdx.x * ROWS_CTA + tid) * 64);
#pragma unroll
        for (int c = 0; c < 16; c++)
            *(float4*)(Xa + tid * X_STRIDE + 4 * c) = z4[c];
    }
    __syncthreads();

    const float t = tptr[0];
    const int lane = tid & 31, wid = tid >> 5;
    const int rg = lane & 7, jg = lane >> 3;
    const int R0 = (wid & 3) * 64 + rg;       // rows R0 + 8*i
    const int J0 = (wid >> 2) * 32 + 8 * jg;  // cols J0 + 0..7

    ull m0 = 0ull, m1 = 0ull, dummy = 0ull;

    // ---- Forward ----
    gemm_fwd<1>(sm,                bc,       Xa, Xb, t, R0, J0, m0);
    __syncthreads();
    gemm_fwd<1>(sm + WT_LAYER,     bc + 128, Xb, Xa, t, R0, J0, m1);
    __syncthreads();
    gemm_fwd<0>(sm + 2 * WT_LAYER, bc + 256, Xa, Xb, t, R0, J0, dummy);
    __syncthreads();

    // ---- z_dot flush (coalesced) ----
    {
        float4* dst = (float4*)(zdot + (size_t)blockIdx.x * ROWS_CTA * 64);
        for (int i4 = tid; i4 < ROWS_CTA * 16; i4 += TPB) {
            int r = i4 >> 4, c = (i4 & 15) << 2;
            dst[i4] = *(const float4*)(Xb + r * X_STRIDE + c);
        }
    }
    __syncthreads();

    // ---- Stage e (row tid) into Xa ----
    {
        const float4* e4 = (const float4*)(e + ((size_t)blockIdx.x * ROWS_CTA + tid) * 64);
#pragma unroll
        for (int c = 0; c < 16; c++)
            *(float4*)(Xa + tid * X_STRIDE + 4 * c) = e4[c];
    }
    __syncthreads();

    // ---- Backward chain: u = D0(W0c e); y = D1(W1c u); p = W2c y ----
    gemm_bwd<1>(sm,                Xa, Xb, R0, J0, m0);
    __syncthreads();
    gemm_bwd<1>(sm + WT_LAYER,     Xb, Xa, R0, J0, m1);
    __syncthreads();
    gemm_bwd<0>(sm + 2 * WT_LAYER, Xa, Xb, R0, J0, 0ull);
    __syncthreads();

    // ---- negdiv: div = e . p  (row tid; e re-read from gmem, L2-resident) ----
    {
        const int r = tid;
        const float4* e4 = (const float4*)(e + ((size_t)blockIdx.x * ROWS_CTA + r) * 64);
        ull dp = 0ull;
#pragma unroll
        for (int c = 0; c < 16; c++) {
            float4 ev = e4[c];
            float4 pv = *(const float4*)(Xb + r * X_STRIDE + 4 * c);
            ffma2(dp, pack2(ev.x, ev.y), pack2(pv.x, pv.y));
            ffma2(dp, pack2(ev.z, ev.w), pack2(pv.z, pv.w));
        }
        negdiv[(size_t)blockIdx.x * ROWS_CTA + r] = -pairsum(dp);
    }
}

extern "C" void kernel_launch(void* const* d_in, const int* in_sizes, int n_in,
                              void* d_out, int out_size) {
    const float* t  = (const float*)d_in[0];
    const float* z  = (const float*)d_in[1];
    const float* e  = (const float*)d_in[2];
    const float* W0 = (const float*)d_in[3];
    const float* b0 = (const float*)d_in[4];
    const float* W1 = (const float*)d_in[5];
    const float* b1 = (const float*)d_in[6];
    const float* W2 = (const float*)d_in[7];
    const float* b2 = (const float*)d_in[8];

    float* zdot = (float*)d_out;                       // [B, 64]
    float* negdiv = zdot + (size_t)B_TOTAL * 64;       // [B, 1]

    cudaFuncSetAttribute(ode_kernel, cudaFuncAttributeMaxDynamicSharedMemorySize, SMEM_BYTES);
    ode_kernel<<<NBLK, TPB, SMEM_BYTES>>>(t, z, e, W0, b0, W1, b1, W2, b2, zdot, negdiv);
}